// round 6
// baseline (speedup 1.0000x reference)
#include <cuda_runtime.h>
#include <math.h>
#include <stdint.h>

#define IN_F   4096
#define OUT_F  1024
#define BSZ    8192     // B*S
#define COLS   9216     // BSZ + OUT_F  (x block | w block)
#define COLS4  2304     // COLS/4
#define GROUPS 2048     // IN_F/2
#define ROUNDS 12

// ---------------- device scratch (no allocs allowed) ----------------
__device__ __align__(128) float g_a[(size_t)IN_F * COLS];   // ping  (151 MB)
__device__ __align__(128) float g_b[(size_t)IN_F * COLS];   // pong  (151 MB)
__device__ __align__(128) float g_wmats[ROUNDS * GROUPS * 4]; // inv(m)^T per (round,group)
__device__ unsigned g_mm[4];   // encoded minx,maxx,minw,maxw
__device__ float    g_qp[4];   // sx, zpx, sw, zpw

// order-preserving float<->uint encoding for atomic min/max
__device__ __forceinline__ unsigned enc_f(float f) {
    unsigned u = __float_as_uint(f);
    return (u & 0x80000000u) ? ~u : (u | 0x80000000u);
}
__device__ __forceinline__ float dec_f(unsigned k) {
    return __uint_as_float((k & 0x80000000u) ? (k ^ 0x80000000u) : ~k);
}

// ---------------- inv(m)^T via LU w/ partial pivoting (mimics jnp.linalg.inv path) ----------------
__global__ void make_wmats_kernel(const float* __restrict__ mats) {
    int idx = blockIdx.x * blockDim.x + threadIdx.x;
    if (idx >= ROUNDS * GROUPS) return;
    const float* m = mats + (size_t)idx * 4;
    float a = m[0], b = m[1], c = m[2], d = m[3];
    float i00, i01, i10, i11;
    if (fabsf(c) > fabsf(a)) {
        float l   = __fdiv_rn(a, c);
        float u22 = __fmaf_rn(-l, d, b);
        float x2c1 = __fdiv_rn(1.0f, u22);
        float x1c1 = __fdiv_rn(__fmul_rn(-d, x2c1), c);
        float x2c2 = __fdiv_rn(-l, u22);
        float x1c2 = __fdiv_rn(__fmaf_rn(-d, x2c2, 1.0f), c);
        i00 = x1c1; i01 = x1c2; i10 = x2c1; i11 = x2c2;
    } else {
        float l   = __fdiv_rn(c, a);
        float u22 = __fmaf_rn(-l, b, d);
        float x2c1 = __fdiv_rn(-l, u22);
        float x1c1 = __fdiv_rn(__fmaf_rn(-b, x2c1, 1.0f), a);
        float x2c2 = __fdiv_rn(1.0f, u22);
        float x1c2 = __fdiv_rn(__fmul_rn(-b, x2c2), a);
        i00 = x1c1; i01 = x1c2; i10 = x2c1; i11 = x2c2;
    }
    float* o = g_wmats + (size_t)idx * 4;
    o[0] = i00; o[1] = i10; o[2] = i01; o[3] = i11;   // transpose(inv)
}

// ---------------- build transform input: g_a[k][col] = A[c][k] + B[c][k] ----------------
__global__ void prep_kernel(const float* __restrict__ A, const float* __restrict__ Bm,
                            int col0) {
    __shared__ float tile[32][33];
    int c0 = blockIdx.x * 32, k0 = blockIdx.y * 32;
    int tx = threadIdx.x, ty = threadIdx.y;            // 32 x 8
#pragma unroll
    for (int i = ty; i < 32; i += 8) {
        size_t idx = (size_t)(c0 + i) * IN_F + k0 + tx;
        tile[i][tx] = __fadd_rn(A[idx], Bm[idx]);
    }
    __syncthreads();
#pragma unroll
    for (int i = ty; i < 32; i += 8) {
        g_a[(size_t)(k0 + i) * COLS + col0 + c0 + tx] = tile[tx][i];
    }
}

// ---------------- one permutation + 2x2-mix round, NO FMA (XLA fusion emits mul+add) ----
__global__ void round_kernel(int dir, int r, const int* __restrict__ perm,
                             const float* __restrict__ matsx) {
    const float* in  = dir ? g_b : g_a;
    float*       out = dir ? g_a : g_b;
    int g   = blockIdx.y;
    int col = blockIdx.x * 256 + threadIdx.x;          // float4 column index
    if (col >= COLS4) return;
    int pa = __ldg(&perm[2 * g]);
    int pb = __ldg(&perm[2 * g + 1]);
    const float* matsw = g_wmats + (size_t)r * GROUPS * 4;  // device-side symbol ref
    const float* mp = (col < BSZ / 4) ? (matsx + (size_t)g * 4)
                                      : (matsw + (size_t)g * 4);
    float4 m = __ldg((const float4*)mp);
    float4 a = ((const float4*)(in + (size_t)pa * COLS))[col];
    float4 b = ((const float4*)(in + (size_t)pb * COLS))[col];
    // out = rn(rn(m_i0*a) + rn(m_i1*b))  -- separate mul & add, intrinsics forbid contraction
    float4 o0, o1;
    o0.x = __fadd_rn(__fmul_rn(m.x, a.x), __fmul_rn(m.y, b.x));
    o0.y = __fadd_rn(__fmul_rn(m.x, a.y), __fmul_rn(m.y, b.y));
    o0.z = __fadd_rn(__fmul_rn(m.x, a.z), __fmul_rn(m.y, b.z));
    o0.w = __fadd_rn(__fmul_rn(m.x, a.w), __fmul_rn(m.y, b.w));
    o1.x = __fadd_rn(__fmul_rn(m.z, a.x), __fmul_rn(m.w, b.x));
    o1.y = __fadd_rn(__fmul_rn(m.z, a.y), __fmul_rn(m.w, b.y));
    o1.z = __fadd_rn(__fmul_rn(m.z, a.z), __fmul_rn(m.w, b.z));
    o1.w = __fadd_rn(__fmul_rn(m.z, a.w), __fmul_rn(m.w, b.w));
    ((float4*)(out + (size_t)(2 * g)     * COLS))[col] = o0;
    ((float4*)(out + (size_t)(2 * g + 1) * COLS))[col] = o1;
}

// ---------------- min/max (per tensor part) ----------------
__global__ void reset_kernel() {
    if (threadIdx.x == 0) {
        g_mm[0] = 0xFFFFFFFFu; g_mm[1] = 0u;
        g_mm[2] = 0xFFFFFFFFu; g_mm[3] = 0u;
    }
}

__global__ void minmax_kernel() {
    const size_t N4 = (size_t)IN_F * COLS4;
    float mnx = 3.402823e38f, mxx = -3.402823e38f;
    float mnw = 3.402823e38f, mxw = -3.402823e38f;
    for (size_t i = (size_t)blockIdx.x * blockDim.x + threadIdx.x; i < N4;
         i += (size_t)gridDim.x * blockDim.x) {
        float4 v = ((const float4*)g_a)[i];
        float lo = fminf(fminf(v.x, v.y), fminf(v.z, v.w));
        float hi = fmaxf(fmaxf(v.x, v.y), fmaxf(v.z, v.w));
        if ((int)(i % COLS4) < 2048) { mnx = fminf(mnx, lo); mxx = fmaxf(mxx, hi); }
        else                         { mnw = fminf(mnw, lo); mxw = fmaxf(mxw, hi); }
    }
    __shared__ float red[256];
    float vals[4] = {mnx, -mxx, mnw, -mxw};
#pragma unroll
    for (int q = 0; q < 4; q++) {
        red[threadIdx.x] = vals[q];
        __syncthreads();
        for (int s = 128; s > 0; s >>= 1) {
            if (threadIdx.x < s) red[threadIdx.x] = fminf(red[threadIdx.x], red[threadIdx.x + s]);
            __syncthreads();
        }
        if (threadIdx.x == 0) {
            float r = red[0];
            if (q & 1) atomicMax(&g_mm[q], enc_f(-r));
            else       atomicMin(&g_mm[q], enc_f(r));
        }
        __syncthreads();
    }
}

__global__ void qparams_kernel() {
    if (threadIdx.x == 0) {
        float lx = dec_f(g_mm[0]), hx = dec_f(g_mm[1]);
        float sx = __fdiv_rn(__fsub_rn(hx, lx), 255.0f);
        float zx = rintf(__fsub_rn(-128.0f, __fdiv_rn(lx, sx)));
        float lw = dec_f(g_mm[2]), hw = dec_f(g_mm[3]);
        float sw = __fdiv_rn(__fsub_rn(hw, lw), 255.0f);
        float zw = rintf(__fsub_rn(-128.0f, __fdiv_rn(lw, sw)));
        g_qp[0] = sx; g_qp[1] = zx; g_qp[2] = sw; g_qp[3] = zw;
    }
}

__device__ __forceinline__ float quant1(float t, float s, float z) {
    float q = rintf(__fadd_rn(__fdiv_rn(t, s), z));
    q = fminf(fmaxf(q, -128.0f), 127.0f);
    return __fmul_rn(__fsub_rn(q, z), s);
}

// ---------------- quantize+dequantize: g_a -> g_b ----------------
__global__ void quant_kernel() {
    const size_t N4 = (size_t)IN_F * COLS4;
    float sx = g_qp[0], zx = g_qp[1], sw_ = g_qp[2], zw = g_qp[3];
    for (size_t i = (size_t)blockIdx.x * blockDim.x + threadIdx.x; i < N4;
         i += (size_t)gridDim.x * blockDim.x) {
        float4 v = ((const float4*)g_a)[i];
        bool isx = (int)(i % COLS4) < 2048;
        float s = isx ? sx : sw_;
        float z = isx ? zx : zw;
        float4 o;
        o.x = quant1(v.x, s, z);
        o.y = quant1(v.y, s, z);
        o.z = quant1(v.z, s, z);
        o.w = quant1(v.w, s, z);
        ((float4*)g_b)[i] = o;
    }
}

// ---------------- fused 3-panel GEMM, exact fp32 ----------------
// out[c][o] = sum_k dqx*dqw - x*wn - nx*(w+wn)  + bias[o]
__global__ void __launch_bounds__(256, 1)
gemm_kernel(const float* __restrict__ x, const float* __restrict__ w,
            const float* __restrict__ bias, const float* __restrict__ wn,
            const float* __restrict__ nx, float* __restrict__ out) {
    __shared__ float Aq[8][132], Ax[8][132], An[8][132];
    __shared__ float Bq[8][132], Bn[8][132], Bw[8][132];
    const int t  = threadIdx.x;
    const int bm = blockIdx.y, bn = blockIdx.x;
    const int tx = t & 15, ty = t >> 4;
    const int kr = t >> 5;           // 0..7
    const int c4 = (t & 31) * 4;     // 0..124
    const int cc = t >> 1;           // 0..127
    const int kq = (t & 1) * 4;      // 0 or 4
    const int row_m = bm * 128, col_n = bn * 128;

    float acc[8][8];
#pragma unroll
    for (int i = 0; i < 8; i++)
#pragma unroll
        for (int j = 0; j < 8; j++) acc[i][j] = 0.0f;

    for (int kt = 0; kt < IN_F; kt += 8) {
        float4 vq  = *(const float4*)&g_b[(size_t)(kt + kr) * COLS + row_m + c4];
        float4 vbq = *(const float4*)&g_b[(size_t)(kt + kr) * COLS + BSZ + col_n + c4];
        float4 vx  = *(const float4*)&x [(size_t)(row_m + cc) * IN_F + kt + kq];
        float4 vnx = *(const float4*)&nx[(size_t)(row_m + cc) * IN_F + kt + kq];
        float4 vwn = *(const float4*)&wn[(size_t)(col_n + cc) * IN_F + kt + kq];
        float4 vw  = *(const float4*)&w [(size_t)(col_n + cc) * IN_F + kt + kq];
        __syncthreads();
        *(float4*)&Aq[kr][c4] = vq;
        *(float4*)&Bq[kr][c4] = vbq;
        // panels exactly as the reference feeds its matmuls: x, nx, wn, w_plus=(w+wn)
        Ax[kq + 0][cc] = vx.x;  Ax[kq + 1][cc] = vx.y;
        Ax[kq + 2][cc] = vx.z;  Ax[kq + 3][cc] = vx.w;
        An[kq + 0][cc] = vnx.x; An[kq + 1][cc] = vnx.y;
        An[kq + 2][cc] = vnx.z; An[kq + 3][cc] = vnx.w;
        Bn[kq + 0][cc] = vwn.x; Bn[kq + 1][cc] = vwn.y;
        Bn[kq + 2][cc] = vwn.z; Bn[kq + 3][cc] = vwn.w;
        Bw[kq + 0][cc] = __fadd_rn(vw.x, vwn.x);
        Bw[kq + 1][cc] = __fadd_rn(vw.y, vwn.y);
        Bw[kq + 2][cc] = __fadd_rn(vw.z, vwn.z);
        Bw[kq + 3][cc] = __fadd_rn(vw.w, vwn.w);
        __syncthreads();
#pragma unroll
        for (int kk = 0; kk < 8; kk++) {
            float aq[8], ax[8], an[8], bq[8], bwn[8], bw[8];
            *(float4*)&aq[0]  = *(const float4*)&Aq[kk][ty * 8];
            *(float4*)&aq[4]  = *(const float4*)&Aq[kk][ty * 8 + 4];
            *(float4*)&ax[0]  = *(const float4*)&Ax[kk][ty * 8];
            *(float4*)&ax[4]  = *(const float4*)&Ax[kk][ty * 8 + 4];
            *(float4*)&an[0]  = *(const float4*)&An[kk][ty * 8];
            *(float4*)&an[4]  = *(const float4*)&An[kk][ty * 8 + 4];
            *(float4*)&bq[0]  = *(const float4*)&Bq[kk][tx * 8];
            *(float4*)&bq[4]  = *(const float4*)&Bq[kk][tx * 8 + 4];
            *(float4*)&bwn[0] = *(const float4*)&Bn[kk][tx * 8];
            *(float4*)&bwn[4] = *(const float4*)&Bn[kk][tx * 8 + 4];
            *(float4*)&bw[0]  = *(const float4*)&Bw[kk][tx * 8];
            *(float4*)&bw[4]  = *(const float4*)&Bw[kk][tx * 8 + 4];
#pragma unroll
            for (int i = 0; i < 8; i++)
#pragma unroll
                for (int j = 0; j < 8; j++) {
                    acc[i][j] = fmaf(aq[i], bq[j], acc[i][j]);
                    acc[i][j] = fmaf(-ax[i], bwn[j], acc[i][j]);
                    acc[i][j] = fmaf(-an[i], bw[j], acc[i][j]);
                }
        }
    }
    float bj[8];
#pragma unroll
    for (int j = 0; j < 8; j++) bj[j] = bias[col_n + tx * 8 + j];
#pragma unroll
    for (int i = 0; i < 8; i++) {
        size_t r = (size_t)(row_m + ty * 8 + i) * OUT_F + col_n + tx * 8;
        float4 o0, o1;
        o0.x = __fadd_rn(acc[i][0], bj[0]); o0.y = __fadd_rn(acc[i][1], bj[1]);
        o0.z = __fadd_rn(acc[i][2], bj[2]); o0.w = __fadd_rn(acc[i][3], bj[3]);
        o1.x = __fadd_rn(acc[i][4], bj[4]); o1.y = __fadd_rn(acc[i][5], bj[5]);
        o1.z = __fadd_rn(acc[i][6], bj[6]); o1.w = __fadd_rn(acc[i][7], bj[7]);
        *(float4*)&out[r]     = o0;
        *(float4*)&out[r + 4] = o1;
    }
}

// ---------------- launch ----------------
extern "C" void kernel_launch(void* const* d_in, const int* in_sizes, int n_in,
                              void* d_out, int out_size) {
    const float* x    = (const float*)d_in[0];
    const float* wgt  = (const float*)d_in[1];
    const float* bias = (const float*)d_in[2];
    const float* wn   = (const float*)d_in[3];
    const float* nx   = (const float*)d_in[4];
    const int*   perms= (const int*)  d_in[5];
    const float* mats = (const float*)d_in[6];
    float* out = (float*)d_out;

    make_wmats_kernel<<<(ROUNDS * GROUPS + 255) / 256, 256>>>(mats);

    prep_kernel<<<dim3(BSZ / 32, IN_F / 32), dim3(32, 8)>>>(x, nx, 0);
    prep_kernel<<<dim3(OUT_F / 32, IN_F / 32), dim3(32, 8)>>>(wgt, wn, BSZ);

    for (int r = 0; r < ROUNDS; r++) {
        round_kernel<<<dim3((COLS4 + 255) / 256, GROUPS), 256>>>(
            r & 1, r, perms + r * IN_F, mats + (size_t)r * GROUPS * 4);
    }

    reset_kernel<<<1, 32>>>();
    minmax_kernel<<<1024, 256>>>();
    qparams_kernel<<<1, 32>>>();
    quant_kernel<<<2048, 256>>>();

    gemm_kernel<<<dim3(OUT_F / 128, BSZ / 128), 256>>>(x, wgt, bias, wn, nx, out);
}

// round 7
// speedup vs baseline: 1.7058x; 1.7058x over previous
#include <cuda_runtime.h>
#include <cuda_bf16.h>
#include <math.h>
#include <stdint.h>

#define IN_F   4096
#define OUT_F  1024
#define BSZ    8192     // B*S
#define COLS   9216     // BSZ + OUT_F  (x block | w block)
#define COLS4  2304     // COLS/4
#define GROUPS 2048     // IN_F/2
#define ROUNDS 12

// ---------------- device scratch (no allocs allowed) ----------------
__device__ __align__(128) float g_a[(size_t)IN_F * COLS];   // ping  (151 MB)
__device__ __align__(128) float g_b[(size_t)IN_F * COLS];   // pong  (151 MB)
__device__ __align__(128) float g_wmats[ROUNDS * GROUPS * 4];
__device__ unsigned g_mm[4];
__device__ float    g_qp[4];   // sx, zpx, sw, zpw

// bf16 GEMM operand panels (all K-major rows of length IN_F)
__device__ __align__(128) __nv_bfloat16 g_qx  [(size_t)BSZ   * IN_F];
__device__ __align__(128) __nv_bfloat16 g_qw  [(size_t)OUT_F * IN_F];
__device__ __align__(128) __nv_bfloat16 g_xhi [(size_t)BSZ   * IN_F];
__device__ __align__(128) __nv_bfloat16 g_xlo [(size_t)BSZ   * IN_F];
__device__ __align__(128) __nv_bfloat16 g_nxhi[(size_t)BSZ   * IN_F];
__device__ __align__(128) __nv_bfloat16 g_nxlo[(size_t)BSZ   * IN_F];
__device__ __align__(128) __nv_bfloat16 g_wnhi[(size_t)OUT_F * IN_F];
__device__ __align__(128) __nv_bfloat16 g_wnlo[(size_t)OUT_F * IN_F];
__device__ __align__(128) __nv_bfloat16 g_wphi[(size_t)OUT_F * IN_F];
__device__ __align__(128) __nv_bfloat16 g_wplo[(size_t)OUT_F * IN_F];

__device__ __forceinline__ unsigned enc_f(float f) {
    unsigned u = __float_as_uint(f);
    return (u & 0x80000000u) ? ~u : (u | 0x80000000u);
}
__device__ __forceinline__ float dec_f(unsigned k) {
    return __uint_as_float((k & 0x80000000u) ? (k ^ 0x80000000u) : ~k);
}

// ---------------- inv(m)^T via LU w/ partial pivoting ----------------
__global__ void make_wmats_kernel(const float* __restrict__ mats) {
    int idx = blockIdx.x * blockDim.x + threadIdx.x;
    if (idx >= ROUNDS * GROUPS) return;
    const float* m = mats + (size_t)idx * 4;
    float a = m[0], b = m[1], c = m[2], d = m[3];
    float i00, i01, i10, i11;
    if (fabsf(c) > fabsf(a)) {
        float l   = __fdiv_rn(a, c);
        float u22 = __fmaf_rn(-l, d, b);
        float x2c1 = __fdiv_rn(1.0f, u22);
        float x1c1 = __fdiv_rn(__fmul_rn(-d, x2c1), c);
        float x2c2 = __fdiv_rn(-l, u22);
        float x1c2 = __fdiv_rn(__fmaf_rn(-d, x2c2, 1.0f), c);
        i00 = x1c1; i01 = x1c2; i10 = x2c1; i11 = x2c2;
    } else {
        float l   = __fdiv_rn(c, a);
        float u22 = __fmaf_rn(-l, b, d);
        float x2c1 = __fdiv_rn(-l, u22);
        float x1c1 = __fdiv_rn(__fmaf_rn(-b, x2c1, 1.0f), a);
        float x2c2 = __fdiv_rn(1.0f, u22);
        float x1c2 = __fdiv_rn(__fmul_rn(-b, x2c2), a);
        i00 = x1c1; i01 = x1c2; i10 = x2c1; i11 = x2c2;
    }
    float* o = g_wmats + (size_t)idx * 4;
    o[0] = i00; o[1] = i10; o[2] = i01; o[3] = i11;
}

// ---------------- build transform input (transpose + add) ----------------
__global__ void prep_kernel(const float* __restrict__ A, const float* __restrict__ Bm,
                            int col0) {
    __shared__ float tile[32][33];
    int c0 = blockIdx.x * 32, k0 = blockIdx.y * 32;
    int tx = threadIdx.x, ty = threadIdx.y;
#pragma unroll
    for (int i = ty; i < 32; i += 8) {
        size_t idx = (size_t)(c0 + i) * IN_F + k0 + tx;
        tile[i][tx] = __fadd_rn(A[idx], Bm[idx]);
    }
    __syncthreads();
#pragma unroll
    for (int i = ty; i < 32; i += 8) {
        g_a[(size_t)(k0 + i) * COLS + col0 + c0 + tx] = tile[tx][i];
    }
}

// ---------------- one permutation + 2x2-mix round (NO FMA) ----------------
__global__ void round_kernel(int dir, int r, const int* __restrict__ perm,
                             const float* __restrict__ matsx) {
    const float* in  = dir ? g_b : g_a;
    float*       out = dir ? g_a : g_b;
    int g   = blockIdx.y;
    int col = blockIdx.x * 256 + threadIdx.x;
    if (col >= COLS4) return;
    int pa = __ldg(&perm[2 * g]);
    int pb = __ldg(&perm[2 * g + 1]);
    const float* matsw = g_wmats + (size_t)r * GROUPS * 4;
    const float* mp = (col < BSZ / 4) ? (matsx + (size_t)g * 4)
                                      : (matsw + (size_t)g * 4);
    float4 m = __ldg((const float4*)mp);
    float4 a = ((const float4*)(in + (size_t)pa * COLS))[col];
    float4 b = ((const float4*)(in + (size_t)pb * COLS))[col];
    float4 o0, o1;
    o0.x = __fadd_rn(__fmul_rn(m.x, a.x), __fmul_rn(m.y, b.x));
    o0.y = __fadd_rn(__fmul_rn(m.x, a.y), __fmul_rn(m.y, b.y));
    o0.z = __fadd_rn(__fmul_rn(m.x, a.z), __fmul_rn(m.y, b.z));
    o0.w = __fadd_rn(__fmul_rn(m.x, a.w), __fmul_rn(m.y, b.w));
    o1.x = __fadd_rn(__fmul_rn(m.z, a.x), __fmul_rn(m.w, b.x));
    o1.y = __fadd_rn(__fmul_rn(m.z, a.y), __fmul_rn(m.w, b.y));
    o1.z = __fadd_rn(__fmul_rn(m.z, a.z), __fmul_rn(m.w, b.z));
    o1.w = __fadd_rn(__fmul_rn(m.z, a.w), __fmul_rn(m.w, b.w));
    ((float4*)(out + (size_t)(2 * g)     * COLS))[col] = o0;
    ((float4*)(out + (size_t)(2 * g + 1) * COLS))[col] = o1;
}

// ---------------- min/max + qparams ----------------
__global__ void reset_kernel() {
    if (threadIdx.x == 0) {
        g_mm[0] = 0xFFFFFFFFu; g_mm[1] = 0u;
        g_mm[2] = 0xFFFFFFFFu; g_mm[3] = 0u;
    }
}

__global__ void minmax_kernel() {
    const size_t N4 = (size_t)IN_F * COLS4;
    float mnx = 3.402823e38f, mxx = -3.402823e38f;
    float mnw = 3.402823e38f, mxw = -3.402823e38f;
    for (size_t i = (size_t)blockIdx.x * blockDim.x + threadIdx.x; i < N4;
         i += (size_t)gridDim.x * blockDim.x) {
        float4 v = ((const float4*)g_a)[i];
        float lo = fminf(fminf(v.x, v.y), fminf(v.z, v.w));
        float hi = fmaxf(fmaxf(v.x, v.y), fmaxf(v.z, v.w));
        if ((int)(i % COLS4) < 2048) { mnx = fminf(mnx, lo); mxx = fmaxf(mxx, hi); }
        else                         { mnw = fminf(mnw, lo); mxw = fmaxf(mxw, hi); }
    }
    __shared__ float red[256];
    float vals[4] = {mnx, -mxx, mnw, -mxw};
#pragma unroll
    for (int q = 0; q < 4; q++) {
        red[threadIdx.x] = vals[q];
        __syncthreads();
        for (int s = 128; s > 0; s >>= 1) {
            if (threadIdx.x < s) red[threadIdx.x] = fminf(red[threadIdx.x], red[threadIdx.x + s]);
            __syncthreads();
        }
        if (threadIdx.x == 0) {
            float r = red[0];
            if (q & 1) atomicMax(&g_mm[q], enc_f(-r));
            else       atomicMin(&g_mm[q], enc_f(r));
        }
        __syncthreads();
    }
}

__global__ void qparams_kernel() {
    if (threadIdx.x == 0) {
        float lx = dec_f(g_mm[0]), hx = dec_f(g_mm[1]);
        float sx = __fdiv_rn(__fsub_rn(hx, lx), 255.0f);
        float zx = rintf(__fsub_rn(-128.0f, __fdiv_rn(lx, sx)));
        float lw = dec_f(g_mm[2]), hw = dec_f(g_mm[3]);
        float sw = __fdiv_rn(__fsub_rn(hw, lw), 255.0f);
        float zw = rintf(__fsub_rn(-128.0f, __fdiv_rn(lw, sw)));
        g_qp[0] = sx; g_qp[1] = zx; g_qp[2] = sw; g_qp[3] = zw;
    }
}

// ---------------- quantize -> integer (q - zp) bf16, transposed to K-major ----------------
__global__ void quantT_kernel() {
    __shared__ float tile[32][33];
    int c0 = blockIdx.x * 32, k0 = blockIdx.y * 32;
    int tx = threadIdx.x, ty = threadIdx.y;   // 32 x 8
    bool isx = (c0 < BSZ);
    float s = isx ? g_qp[0] : g_qp[2];
    float z = isx ? g_qp[1] : g_qp[3];
#pragma unroll
    for (int i = ty; i < 32; i += 8) {
        float t = g_a[(size_t)(k0 + i) * COLS + c0 + tx];
        float q = rintf(__fadd_rn(__fdiv_rn(t, s), z));
        q = fminf(fmaxf(q, -128.0f), 127.0f);
        tile[i][tx] = __fsub_rn(q, z);     // exact integer in [-255,255]
    }
    __syncthreads();
    __nv_bfloat16* dst = isx ? g_qx : g_qw;
    int cb = isx ? c0 : (c0 - BSZ);
#pragma unroll
    for (int i = ty; i < 32; i += 8) {
        dst[(size_t)(cb + i) * IN_F + k0 + tx] = __float2bfloat16_rn(tile[tx][i]);
    }
}

// ---------------- bf16 hi/lo split of x, nx ----------------
__global__ void split_x_kernel(const float* __restrict__ x, const float* __restrict__ nx) {
    const size_t N4 = (size_t)BSZ * IN_F / 4;
    for (size_t i = (size_t)blockIdx.x * blockDim.x + threadIdx.x; i < N4;
         i += (size_t)gridDim.x * blockDim.x) {
        float4 vx = ((const float4*)x)[i];
        float4 vn = ((const float4*)nx)[i];
        __nv_bfloat16 h[4], l[4];
        h[0] = __float2bfloat16_rn(vx.x); l[0] = __float2bfloat16_rn(__fsub_rn(vx.x, __bfloat162float(h[0])));
        h[1] = __float2bfloat16_rn(vx.y); l[1] = __float2bfloat16_rn(__fsub_rn(vx.y, __bfloat162float(h[1])));
        h[2] = __float2bfloat16_rn(vx.z); l[2] = __float2bfloat16_rn(__fsub_rn(vx.z, __bfloat162float(h[2])));
        h[3] = __float2bfloat16_rn(vx.w); l[3] = __float2bfloat16_rn(__fsub_rn(vx.w, __bfloat162float(h[3])));
        ((uint2*)g_xhi)[i] = *(uint2*)h;
        ((uint2*)g_xlo)[i] = *(uint2*)l;
        h[0] = __float2bfloat16_rn(vn.x); l[0] = __float2bfloat16_rn(__fsub_rn(vn.x, __bfloat162float(h[0])));
        h[1] = __float2bfloat16_rn(vn.y); l[1] = __float2bfloat16_rn(__fsub_rn(vn.y, __bfloat162float(h[1])));
        h[2] = __float2bfloat16_rn(vn.z); l[2] = __float2bfloat16_rn(__fsub_rn(vn.z, __bfloat162float(h[2])));
        h[3] = __float2bfloat16_rn(vn.w); l[3] = __float2bfloat16_rn(__fsub_rn(vn.w, __bfloat162float(h[3])));
        ((uint2*)g_nxhi)[i] = *(uint2*)h;
        ((uint2*)g_nxlo)[i] = *(uint2*)l;
    }
}

// ---------------- bf16 hi/lo split of wn, w+wn ----------------
__global__ void split_w_kernel(const float* __restrict__ w, const float* __restrict__ wn) {
    const size_t N4 = (size_t)OUT_F * IN_F / 4;
    for (size_t i = (size_t)blockIdx.x * blockDim.x + threadIdx.x; i < N4;
         i += (size_t)gridDim.x * blockDim.x) {
        float4 vw = ((const float4*)w)[i];
        float4 vn = ((const float4*)wn)[i];
        __nv_bfloat16 h[4], l[4];
        h[0] = __float2bfloat16_rn(vn.x); l[0] = __float2bfloat16_rn(__fsub_rn(vn.x, __bfloat162float(h[0])));
        h[1] = __float2bfloat16_rn(vn.y); l[1] = __float2bfloat16_rn(__fsub_rn(vn.y, __bfloat162float(h[1])));
        h[2] = __float2bfloat16_rn(vn.z); l[2] = __float2bfloat16_rn(__fsub_rn(vn.z, __bfloat162float(h[2])));
        h[3] = __float2bfloat16_rn(vn.w); l[3] = __float2bfloat16_rn(__fsub_rn(vn.w, __bfloat162float(h[3])));
        ((uint2*)g_wnhi)[i] = *(uint2*)h;
        ((uint2*)g_wnlo)[i] = *(uint2*)l;
        float p0 = __fadd_rn(vw.x, vn.x), p1 = __fadd_rn(vw.y, vn.y);
        float p2 = __fadd_rn(vw.z, vn.z), p3 = __fadd_rn(vw.w, vn.w);
        h[0] = __float2bfloat16_rn(p0); l[0] = __float2bfloat16_rn(__fsub_rn(p0, __bfloat162float(h[0])));
        h[1] = __float2bfloat16_rn(p1); l[1] = __float2bfloat16_rn(__fsub_rn(p1, __bfloat162float(h[1])));
        h[2] = __float2bfloat16_rn(p2); l[2] = __float2bfloat16_rn(__fsub_rn(p2, __bfloat162float(h[2])));
        h[3] = __float2bfloat16_rn(p3); l[3] = __float2bfloat16_rn(__fsub_rn(p3, __bfloat162float(h[3])));
        ((uint2*)g_wphi)[i] = *(uint2*)h;
        ((uint2*)g_wplo)[i] = *(uint2*)l;
    }
}

// ---------------- bf16 mma.sync GEMM over 7 virtual K-segments ----------------
// segs: 0:(qx,qw)->acc_q ; 1..6: (xhi,wnhi)(xhi,wnlo)(xlo,wnhi)(nxhi,wphi)(nxhi,wplo)(nxlo,wphi)
// out = bias - [ -sxsw*Sum_q + Sum_corr ]
#define N_ITERS (7 * 128)

__global__ void __launch_bounds__(256)
gemm_bf16_kernel(const float* __restrict__ bias, float* __restrict__ out) {
    __shared__ __nv_bfloat16 As[2][128][48];
    __shared__ __nv_bfloat16 Bs[2][128][48];
    const int t = threadIdx.x, lane = t & 31, warp = t >> 5;
    const int bn = blockIdx.x, bm = blockIdx.y;
    const int wm = (warp >> 2) * 64, wn = (warp & 3) * 32;

    float acc[4][4][4];
#pragma unroll
    for (int a = 0; a < 4; a++)
#pragma unroll
        for (int b = 0; b < 4; b++)
#pragma unroll
            for (int c = 0; c < 4; c++) acc[a][b][c] = 0.0f;

    const float sxsw = __fmul_rn(g_qp[0], g_qp[2]);

    auto load_tile = [&](int buf, int it) {
        int seg = it >> 7;
        int kt  = (it & 127) << 5;
        const __nv_bfloat16 *pa, *pb;
        switch (seg) {
            case 0:  pa = g_qx;   pb = g_qw;   break;
            case 1:  pa = g_xhi;  pb = g_wnhi; break;
            case 2:  pa = g_xhi;  pb = g_wnlo; break;
            case 3:  pa = g_xlo;  pb = g_wnhi; break;
            case 4:  pa = g_nxhi; pb = g_wphi; break;
            case 5:  pa = g_nxhi; pb = g_wplo; break;
            default: pa = g_nxlo; pb = g_wphi; break;
        }
#pragma unroll
        for (int u = 0; u < 2; u++) {
            int q = t * 2 + u;
            int row = q >> 2, ch = (q & 3) * 8;
            const __nv_bfloat16* ga = pa + (size_t)(bm * 128 + row) * IN_F + kt + ch;
            uint32_t sa = (uint32_t)__cvta_generic_to_shared(&As[buf][row][ch]);
            asm volatile("cp.async.cg.shared.global [%0],[%1],16;\n" :: "r"(sa), "l"(ga));
            const __nv_bfloat16* gb = pb + (size_t)(bn * 128 + row) * IN_F + kt + ch;
            uint32_t sb = (uint32_t)__cvta_generic_to_shared(&Bs[buf][row][ch]);
            asm volatile("cp.async.cg.shared.global [%0],[%1],16;\n" :: "r"(sb), "l"(gb));
        }
    };

    load_tile(0, 0);
    asm volatile("cp.async.commit_group;\n" ::);

    for (int it = 0; it < N_ITERS; it++) {
        asm volatile("cp.async.wait_group 0;\n" ::);
        __syncthreads();
        int buf = it & 1;
        if (it + 1 < N_ITERS) load_tile(buf ^ 1, it + 1);
        asm volatile("cp.async.commit_group;\n" ::);

#pragma unroll
        for (int kc = 0; kc < 32; kc += 16) {
            uint32_t af[4][4], bf[4][2];
#pragma unroll
            for (int mt = 0; mt < 4; mt++) {
                uint32_t ad = (uint32_t)__cvta_generic_to_shared(
                    &As[buf][wm + mt * 16 + (lane & 15)][kc + (lane >> 4) * 8]);
                asm volatile("ldmatrix.sync.aligned.m8n8.x4.shared.b16 {%0,%1,%2,%3},[%4];"
                             : "=r"(af[mt][0]), "=r"(af[mt][1]), "=r"(af[mt][2]), "=r"(af[mt][3])
                             : "r"(ad));
            }
#pragma unroll
            for (int nt = 0; nt < 4; nt++) {
                uint32_t bd = (uint32_t)__cvta_generic_to_shared(
                    &Bs[buf][wn + nt * 8 + (lane & 7)][kc + ((lane >> 3) & 1) * 8]);
                asm volatile("ldmatrix.sync.aligned.m8n8.x2.shared.b16 {%0,%1},[%2];"
                             : "=r"(bf[nt][0]), "=r"(bf[nt][1]) : "r"(bd));
            }
#pragma unroll
            for (int mt = 0; mt < 4; mt++)
#pragma unroll
                for (int nt = 0; nt < 4; nt++) {
                    asm volatile(
                        "mma.sync.aligned.m16n8k16.row.col.f32.bf16.bf16.f32 "
                        "{%0,%1,%2,%3},{%4,%5,%6,%7},{%8,%9},{%0,%1,%2,%3};"
                        : "+f"(acc[mt][nt][0]), "+f"(acc[mt][nt][1]),
                          "+f"(acc[mt][nt][2]), "+f"(acc[mt][nt][3])
                        : "r"(af[mt][0]), "r"(af[mt][1]), "r"(af[mt][2]), "r"(af[mt][3]),
                          "r"(bf[nt][0]), "r"(bf[nt][1]));
                }
        }
        if (it == 127) {   // end of quantized segment: fold scale, flip sign
            float nss = -sxsw;
#pragma unroll
            for (int a = 0; a < 4; a++)
#pragma unroll
                for (int b = 0; b < 4; b++)
#pragma unroll
                    for (int c = 0; c < 4; c++) acc[a][b][c] = __fmul_rn(acc[a][b][c], nss);
        }
    }

    // epilogue: out = bias - acc
    const int grp = lane >> 2, tig = lane & 3;
#pragma unroll
    for (int mt = 0; mt < 4; mt++)
#pragma unroll
        for (int nt = 0; nt < 4; nt++) {
            int gm = bm * 128 + wm + mt * 16 + grp;
            int gn = bn * 128 + wn + nt * 8 + tig * 2;
            float b0 = bias[gn], b1 = bias[gn + 1];
            float2 v0, v1;
            v0.x = __fsub_rn(b0, acc[mt][nt][0]);
            v0.y = __fsub_rn(b1, acc[mt][nt][1]);
            v1.x = __fsub_rn(b0, acc[mt][nt][2]);
            v1.y = __fsub_rn(b1, acc[mt][nt][3]);
            *(float2*)&out[(size_t)gm * OUT_F + gn]       = v0;
            *(float2*)&out[(size_t)(gm + 8) * OUT_F + gn] = v1;
        }
}

// ---------------- launch ----------------
extern "C" void kernel_launch(void* const* d_in, const int* in_sizes, int n_in,
                              void* d_out, int out_size) {
    const float* x    = (const float*)d_in[0];
    const float* wgt  = (const float*)d_in[1];
    const float* bias = (const float*)d_in[2];
    const float* wn   = (const float*)d_in[3];
    const float* nx   = (const float*)d_in[4];
    const int*   perms= (const int*)  d_in[5];
    const float* mats = (const float*)d_in[6];
    float* out = (float*)d_out;

    make_wmats_kernel<<<(ROUNDS * GROUPS + 255) / 256, 256>>>(mats);

    // bf16 splits (independent of transform)
    split_x_kernel<<<4096, 256>>>(x, nx);
    split_w_kernel<<<512, 256>>>(wgt, wn);

    prep_kernel<<<dim3(BSZ / 32, IN_F / 32), dim3(32, 8)>>>(x, nx, 0);
    prep_kernel<<<dim3(OUT_F / 32, IN_F / 32), dim3(32, 8)>>>(wgt, wn, BSZ);

    for (int r = 0; r < ROUNDS; r++) {
        round_kernel<<<dim3((COLS4 + 255) / 256, GROUPS), 256>>>(
            r & 1, r, perms + r * IN_F, mats + (size_t)r * GROUPS * 4);
    }

    reset_kernel<<<1, 32>>>();
    minmax_kernel<<<1024, 256>>>();
    qparams_kernel<<<1, 32>>>();
    quantT_kernel<<<dim3(COLS / 32, IN_F / 32), dim3(32, 8)>>>();

    gemm_bf16_kernel<<<dim3(OUT_F / 128, BSZ / 128), 256>>>(bias, out);
}

// round 9
// speedup vs baseline: 2.6773x; 1.5695x over previous
#include <cuda_runtime.h>
#include <cuda.h>
#include <cuda_bf16.h>
#include <math.h>
#include <stdint.h>

#define IN_F   4096
#define OUT_F  1024
#define BSZ    8192
#define COLS   9216
#define COLS4  2304
#define GROUPS 2048
#define ROUNDS 12

#define KCH    64
#define CHPS   64             // chunks per segment (4096/64)
#define NSEG   7
#define NCH    (NSEG * CHPS)  // 448
#define NSTG   3
#define CH_BYTES (16384 + 16384)   // A 128x64 bf16 + B 128x64 bf16

// smem: [0,24) mbarriers, stage data at 1024 + s*32768 (A 16KB | B 16KB)
#define DSMEM (1024 + NSTG * 32768)

// ---------------- device scratch ----------------
__device__ __align__(128) float g_a[(size_t)IN_F * COLS];
__device__ __align__(128) float g_b[(size_t)IN_F * COLS];
__device__ __align__(128) float g_wmats[ROUNDS * GROUPS * 4];
__device__ unsigned g_mm[4];
__device__ float    g_qp[4];

__device__ __align__(128) __nv_bfloat16 g_qx  [(size_t)BSZ   * IN_F];
__device__ __align__(128) __nv_bfloat16 g_qw  [(size_t)OUT_F * IN_F];
__device__ __align__(128) __nv_bfloat16 g_xhi [(size_t)BSZ   * IN_F];
__device__ __align__(128) __nv_bfloat16 g_xlo [(size_t)BSZ   * IN_F];
__device__ __align__(128) __nv_bfloat16 g_nxhi[(size_t)BSZ   * IN_F];
__device__ __align__(128) __nv_bfloat16 g_nxlo[(size_t)BSZ   * IN_F];
__device__ __align__(128) __nv_bfloat16 g_wnhi[(size_t)OUT_F * IN_F];
__device__ __align__(128) __nv_bfloat16 g_wnlo[(size_t)OUT_F * IN_F];
__device__ __align__(128) __nv_bfloat16 g_wphi[(size_t)OUT_F * IN_F];
__device__ __align__(128) __nv_bfloat16 g_wplo[(size_t)OUT_F * IN_F];

struct TmapPack { CUtensorMap a[5]; CUtensorMap b[5]; };

// ---------------- helpers ----------------
__device__ __forceinline__ unsigned enc_f(float f) {
    unsigned u = __float_as_uint(f);
    return (u & 0x80000000u) ? ~u : (u | 0x80000000u);
}
__device__ __forceinline__ float dec_f(unsigned k) {
    return __uint_as_float((k & 0x80000000u) ? (k ^ 0x80000000u) : ~k);
}
__device__ __forceinline__ uint32_t smem_u32(const void* p) {
    uint32_t a;
    asm("{ .reg .u64 t; cvta.to.shared.u64 t, %1; cvt.u32.u64 %0, t; }" : "=r"(a) : "l"(p));
    return a;
}

#define MBAR_INIT(addr, cnt) \
    asm volatile("mbarrier.init.shared.b64 [%0], %1;" :: "r"(addr), "r"(cnt) : "memory")
#define MBAR_EXPECT_TX(addr, bytes) \
    asm volatile("mbarrier.arrive.expect_tx.shared.b64 _, [%0], %1;" :: "r"(addr), "r"(bytes) : "memory")
#define MBAR_WAIT(addr, par) do {                                              \
    asm volatile(                                                              \
        "{\n\t.reg .pred P;\n\t"                                               \
        "WL_%=:\n\t"                                                           \
        "mbarrier.try_wait.parity.acquire.cta.shared::cta.b64 P, [%0], %1, 0x989680;\n\t" \
        "@P bra.uni WD_%=;\n\t"                                                \
        "bra.uni WL_%=;\n\t"                                                   \
        "WD_%=:\n\t}"                                                          \
        :: "r"(addr), "r"(par) : "memory");                                    \
} while (0)

#define TMA_2D(smem, map, cx, cy, mbar) \
    asm volatile("cp.async.bulk.tensor.2d.shared::cta.global.tile.mbarrier::complete_tx::bytes " \
                 "[%0], [%1, {%2, %3}], [%4];" \
                 :: "r"(smem), "l"(map), "r"(cx), "r"(cy), "r"(mbar) : "memory")

// ---------------- inv(m)^T via LU w/ partial pivoting ----------------
__global__ void make_wmats_kernel(const float* __restrict__ mats) {
    int idx = blockIdx.x * blockDim.x + threadIdx.x;
    if (idx >= ROUNDS * GROUPS) return;
    const float* m = mats + (size_t)idx * 4;
    float a = m[0], b = m[1], c = m[2], d = m[3];
    float i00, i01, i10, i11;
    if (fabsf(c) > fabsf(a)) {
        float l   = __fdiv_rn(a, c);
        float u22 = __fmaf_rn(-l, d, b);
        float x2c1 = __fdiv_rn(1.0f, u22);
        float x1c1 = __fdiv_rn(__fmul_rn(-d, x2c1), c);
        float x2c2 = __fdiv_rn(-l, u22);
        float x1c2 = __fdiv_rn(__fmaf_rn(-d, x2c2, 1.0f), c);
        i00 = x1c1; i01 = x1c2; i10 = x2c1; i11 = x2c2;
    } else {
        float l   = __fdiv_rn(c, a);
        float u22 = __fmaf_rn(-l, b, d);
        float x2c1 = __fdiv_rn(-l, u22);
        float x1c1 = __fdiv_rn(__fmaf_rn(-b, x2c1, 1.0f), a);
        float x2c2 = __fdiv_rn(1.0f, u22);
        float x1c2 = __fdiv_rn(__fmul_rn(-b, x2c2), a);
        i00 = x1c1; i01 = x1c2; i10 = x2c1; i11 = x2c2;
    }
    float* o = g_wmats + (size_t)idx * 4;
    o[0] = i00; o[1] = i10; o[2] = i01; o[3] = i11;
}

// ---------------- transpose + add ----------------
__global__ void prep_kernel(const float* __restrict__ A, const float* __restrict__ Bm,
                            int col0) {
    __shared__ float tile[32][33];
    int c0 = blockIdx.x * 32, k0 = blockIdx.y * 32;
    int tx = threadIdx.x, ty = threadIdx.y;
#pragma unroll
    for (int i = ty; i < 32; i += 8) {
        size_t idx = (size_t)(c0 + i) * IN_F + k0 + tx;
        tile[i][tx] = __fadd_rn(A[idx], Bm[idx]);
    }
    __syncthreads();
#pragma unroll
    for (int i = ty; i < 32; i += 8) {
        g_a[(size_t)(k0 + i) * COLS + col0 + c0 + tx] = tile[tx][i];
    }
}

// ---------------- permutation + 2x2-mix round (NO FMA) ----------------
__global__ void round_kernel(int dir, int r, const int* __restrict__ perm,
                             const float* __restrict__ matsx) {
    const float* in  = dir ? g_b : g_a;
    float*       out = dir ? g_a : g_b;
    int g   = blockIdx.y;
    int col = blockIdx.x * 256 + threadIdx.x;
    if (col >= COLS4) return;
    int pa = __ldg(&perm[2 * g]);
    int pb = __ldg(&perm[2 * g + 1]);
    const float* matsw = g_wmats + (size_t)r * GROUPS * 4;
    const float* mp = (col < BSZ / 4) ? (matsx + (size_t)g * 4) : (matsw + (size_t)g * 4);
    float4 m = __ldg((const float4*)mp);
    float4 a = ((const float4*)(in + (size_t)pa * COLS))[col];
    float4 b = ((const float4*)(in + (size_t)pb * COLS))[col];
    float4 o0, o1;
    o0.x = __fadd_rn(__fmul_rn(m.x, a.x), __fmul_rn(m.y, b.x));
    o0.y = __fadd_rn(__fmul_rn(m.x, a.y), __fmul_rn(m.y, b.y));
    o0.z = __fadd_rn(__fmul_rn(m.x, a.z), __fmul_rn(m.y, b.z));
    o0.w = __fadd_rn(__fmul_rn(m.x, a.w), __fmul_rn(m.y, b.w));
    o1.x = __fadd_rn(__fmul_rn(m.z, a.x), __fmul_rn(m.w, b.x));
    o1.y = __fadd_rn(__fmul_rn(m.z, a.y), __fmul_rn(m.w, b.y));
    o1.z = __fadd_rn(__fmul_rn(m.z, a.z), __fmul_rn(m.w, b.z));
    o1.w = __fadd_rn(__fmul_rn(m.z, a.w), __fmul_rn(m.w, b.w));
    ((float4*)(out + (size_t)(2 * g)     * COLS))[col] = o0;
    ((float4*)(out + (size_t)(2 * g + 1) * COLS))[col] = o1;
}

// ---------------- min/max + qparams ----------------
__global__ void reset_kernel() {
    if (threadIdx.x == 0) {
        g_mm[0] = 0xFFFFFFFFu; g_mm[1] = 0u;
        g_mm[2] = 0xFFFFFFFFu; g_mm[3] = 0u;
    }
}
__global__ void minmax_kernel() {
    const size_t N4 = (size_t)IN_F * COLS4;
    float mnx = 3.402823e38f, mxx = -3.402823e38f;
    float mnw = 3.402823e38f, mxw = -3.402823e38f;
    for (size_t i = (size_t)blockIdx.x * blockDim.x + threadIdx.x; i < N4;
         i += (size_t)gridDim.x * blockDim.x) {
        float4 v = ((const float4*)g_a)[i];
        float lo = fminf(fminf(v.x, v.y), fminf(v.z, v.w));
        float hi = fmaxf(fmaxf(v.x, v.y), fmaxf(v.z, v.w));
        if ((int)(i % COLS4) < 2048) { mnx = fminf(mnx, lo); mxx = fmaxf(mxx, hi); }
        else                         { mnw = fminf(mnw, lo); mxw = fmaxf(mxw, hi); }
    }
    __shared__ float red[256];
    float vals[4] = {mnx, -mxx, mnw, -mxw};
#pragma unroll
    for (int q = 0; q < 4; q++) {
        red[threadIdx.x] = vals[q];
        __syncthreads();
        for (int s = 128; s > 0; s >>= 1) {
            if (threadIdx.x < s) red[threadIdx.x] = fminf(red[threadIdx.x], red[threadIdx.x + s]);
            __syncthreads();
        }
        if (threadIdx.x == 0) {
            float r = red[0];
            if (q & 1) atomicMax(&g_mm[q], enc_f(-r));
            else       atomicMin(&g_mm[q], enc_f(r));
        }
        __syncthreads();
    }
}
__global__ void qparams_kernel() {
    if (threadIdx.x == 0) {
        float lx = dec_f(g_mm[0]), hx = dec_f(g_mm[1]);
        float sx = __fdiv_rn(__fsub_rn(hx, lx), 255.0f);
        float zx = rintf(__fsub_rn(-128.0f, __fdiv_rn(lx, sx)));
        float lw = dec_f(g_mm[2]), hw = dec_f(g_mm[3]);
        float sw = __fdiv_rn(__fsub_rn(hw, lw), 255.0f);
        float zw = rintf(__fsub_rn(-128.0f, __fdiv_rn(lw, sw)));
        g_qp[0] = sx; g_qp[1] = zx; g_qp[2] = sw; g_qp[3] = zw;
    }
}

// ---------------- quantize -> integer (q - zp) bf16, K-major ----------------
__global__ void quantT_kernel() {
    __shared__ float tile[32][33];
    int c0 = blockIdx.x * 32, k0 = blockIdx.y * 32;
    int tx = threadIdx.x, ty = threadIdx.y;
    bool isx = (c0 < BSZ);
    float s = isx ? g_qp[0] : g_qp[2];
    float z = isx ? g_qp[1] : g_qp[3];
#pragma unroll
    for (int i = ty; i < 32; i += 8) {
        float t = g_a[(size_t)(k0 + i) * COLS + c0 + tx];
        float q = rintf(__fadd_rn(__fdiv_rn(t, s), z));
        q = fminf(fmaxf(q, -128.0f), 127.0f);
        tile[i][tx] = __fsub_rn(q, z);
    }
    __syncthreads();
    __nv_bfloat16* dst = isx ? g_qx : g_qw;
    int cb = isx ? c0 : (c0 - BSZ);
#pragma unroll
    for (int i = ty; i < 32; i += 8) {
        dst[(size_t)(cb + i) * IN_F + k0 + tx] = __float2bfloat16_rn(tile[tx][i]);
    }
}

// ---------------- bf16 hi/lo splits ----------------
__device__ __forceinline__ void split1(float v, __nv_bfloat16& h, __nv_bfloat16& l) {
    h = __float2bfloat16_rn(v);
    l = __float2bfloat16_rn(__fsub_rn(v, __bfloat162float(h)));
}
__global__ void split_x_kernel(const float* __restrict__ x, const float* __restrict__ nx) {
    const size_t N4 = (size_t)BSZ * IN_F / 4;
    for (size_t i = (size_t)blockIdx.x * blockDim.x + threadIdx.x; i < N4;
         i += (size_t)gridDim.x * blockDim.x) {
        float4 vx = ((const float4*)x)[i];
        float4 vn = ((const float4*)nx)[i];
        __nv_bfloat16 h[4], l[4];
        split1(vx.x, h[0], l[0]); split1(vx.y, h[1], l[1]);
        split1(vx.z, h[2], l[2]); split1(vx.w, h[3], l[3]);
        ((uint2*)g_xhi)[i] = *(uint2*)h; ((uint2*)g_xlo)[i] = *(uint2*)l;
        split1(vn.x, h[0], l[0]); split1(vn.y, h[1], l[1]);
        split1(vn.z, h[2], l[2]); split1(vn.w, h[3], l[3]);
        ((uint2*)g_nxhi)[i] = *(uint2*)h; ((uint2*)g_nxlo)[i] = *(uint2*)l;
    }
}
__global__ void split_w_kernel(const float* __restrict__ w, const float* __restrict__ wn) {
    const size_t N4 = (size_t)OUT_F * IN_F / 4;
    for (size_t i = (size_t)blockIdx.x * blockDim.x + threadIdx.x; i < N4;
         i += (size_t)gridDim.x * blockDim.x) {
        float4 vw = ((const float4*)w)[i];
        float4 vn = ((const float4*)wn)[i];
        __nv_bfloat16 h[4], l[4];
        split1(vn.x, h[0], l[0]); split1(vn.y, h[1], l[1]);
        split1(vn.z, h[2], l[2]); split1(vn.w, h[3], l[3]);
        ((uint2*)g_wnhi)[i] = *(uint2*)h; ((uint2*)g_wnlo)[i] = *(uint2*)l;
        float p0 = __fadd_rn(vw.x, vn.x), p1 = __fadd_rn(vw.y, vn.y);
        float p2 = __fadd_rn(vw.z, vn.z), p3 = __fadd_rn(vw.w, vn.w);
        split1(p0, h[0], l[0]); split1(p1, h[1], l[1]);
        split1(p2, h[2], l[2]); split1(p3, h[3], l[3]);
        ((uint2*)g_wphi)[i] = *(uint2*)h; ((uint2*)g_wplo)[i] = *(uint2*)l;
    }
}

// ---------------- TMA-fed mma.sync GEMM ----------------
// segs: 0:(qx,qw) ; 1..6: (xhi,wnhi)(xhi,wnlo)(xlo,wnhi)(nxhi,wphi)(nxhi,wplo)(nxlo,wphi)
// acc = Sum_q ; at seg0 end acc *= -sx*sw ; then acc += corr ; out = bias - acc
__global__ void __launch_bounds__(256)
gemm_tma_kernel(const __grid_constant__ TmapPack tp,
                const float* __restrict__ bias, float* __restrict__ out) {
    extern __shared__ __align__(1024) char smem[];
    uint32_t sb = smem_u32(smem);
    const int tid = threadIdx.x, lane = tid & 31, warp = tid >> 5;
    const int bn = blockIdx.x, bm = blockIdx.y;
    const int wm = (warp >> 2) * 64, wn = (warp & 3) * 32;

    if (tid == 0) {
#pragma unroll
        for (int i = 0; i < NSTG; i++) MBAR_INIT(sb + i * 8, 1);
    }
    __syncthreads();

    float acc[4][4][4];
#pragma unroll
    for (int a = 0; a < 4; a++)
#pragma unroll
        for (int b = 0; b < 4; b++)
#pragma unroll
            for (int c = 0; c < 4; c++) acc[a][b][c] = 0.0f;

    const float nss = -__fmul_rn(g_qp[0], g_qp[2]);

    static const int asel[NSEG] = {0, 1, 1, 2, 3, 3, 4};
    static const int bsel[NSEG] = {0, 1, 2, 1, 3, 4, 3};

    if (tid == 0) {
#pragma unroll
        for (int p = 0; p < NSTG; p++) {
            int seg = p >> 6, kx = (p & 63) * KCH;
            uint32_t st = sb + 1024 + p * 32768;
            MBAR_EXPECT_TX(sb + p * 8, CH_BYTES);
            TMA_2D(st,         &tp.a[asel[seg]], kx, bm * 128, sb + p * 8);
            TMA_2D(st + 16384, &tp.b[bsel[seg]], kx, bn * 128, sb + p * 8);
        }
    }

    for (int c = 0; c < NCH; c++) {
        int s = c % NSTG, ph = (c / NSTG) & 1;
        MBAR_WAIT(sb + s * 8, ph);
        uint32_t abase = sb + 1024 + s * 32768;
        uint32_t bbase = abase + 16384;
#pragma unroll
        for (int kq = 0; kq < 4; kq++) {
            uint32_t af[4][4], bf[4][2];
#pragma unroll
            for (int mt = 0; mt < 4; mt++) {
                int row = wm + mt * 16 + (lane & 15);
                int chk = kq * 2 + (lane >> 4);
                uint32_t off = (uint32_t)(row * 128 + chk * 16);
                uint32_t ad = abase + (off ^ ((off >> 3) & 0x70));
                asm volatile("ldmatrix.sync.aligned.m8n8.x4.shared.b16 {%0,%1,%2,%3},[%4];"
                             : "=r"(af[mt][0]), "=r"(af[mt][1]), "=r"(af[mt][2]), "=r"(af[mt][3])
                             : "r"(ad));
            }
#pragma unroll
            for (int nt = 0; nt < 4; nt++) {
                int row = wn + nt * 8 + (lane & 7);
                int chk = kq * 2 + ((lane >> 3) & 1);
                uint32_t off = (uint32_t)(row * 128 + chk * 16);
                uint32_t bd = bbase + (off ^ ((off >> 3) & 0x70));
                asm volatile("ldmatrix.sync.aligned.m8n8.x2.shared.b16 {%0,%1},[%2];"
                             : "=r"(bf[nt][0]), "=r"(bf[nt][1]) : "r"(bd));
            }
#pragma unroll
            for (int mt = 0; mt < 4; mt++)
#pragma unroll
                for (int nt = 0; nt < 4; nt++) {
                    asm volatile(
                        "mma.sync.aligned.m16n8k16.row.col.f32.bf16.bf16.f32 "
                        "{%0,%1,%2,%3},{%4,%5,%6,%7},{%8,%9},{%0,%1,%2,%3};"
                        : "+f"(acc[mt][nt][0]), "+f"(acc[mt][nt][1]),
                          "+f"(acc[mt][nt][2]), "+f"(acc[mt][nt][3])
                        : "r"(af[mt][0]), "r"(af[mt][1]), "r"(af[mt][2]), "r"(af[mt][3]),
                          "r"(bf[nt][0]), "r"(bf[nt][1]));
                }
        }
        if (c == CHPS - 1) {
#pragma unroll
            for (int a = 0; a < 4; a++)
#pragma unroll
                for (int b = 0; b < 4; b++)
#pragma unroll
                    for (int q = 0; q < 4; q++) acc[a][b][q] = __fmul_rn(acc[a][b][q], nss);
        }
        __syncthreads();
        if (tid == 0 && c + NSTG < NCH) {
            int nc = c + NSTG;
            int seg = nc >> 6, kx = (nc & 63) * KCH;
            uint32_t st = sb + 1024 + s * 32768;
            MBAR_EXPECT_TX(sb + s * 8, CH_BYTES);
            TMA_2D(st,         &tp.a[asel[seg]], kx, bm * 128, sb + s * 8);
            TMA_2D(st + 16384, &tp.b[bsel[seg]], kx, bn * 128, sb + s * 8);
        }
    }

    // epilogue: out = bias - acc
    const int grp = lane >> 2, tig = lane & 3;
#pragma unroll
    for (int mt = 0; mt < 4; mt++)
#pragma unroll
        for (int nt = 0; nt < 4; nt++) {
            int gm = bm * 128 + wm + mt * 16 + grp;
            int gn = bn * 128 + wn + nt * 8 + tig * 2;
            float b0 = bias[gn], b1 = bias[gn + 1];
            float2 v0, v1;
            v0.x = __fsub_rn(b0, acc[mt][nt][0]);
            v0.y = __fsub_rn(b1, acc[mt][nt][1]);
            v1.x = __fsub_rn(b0, acc[mt][nt][2]);
            v1.y = __fsub_rn(b1, acc[mt][nt][3]);
            *(float2*)&out[(size_t)gm * OUT_F + gn]       = v0;
            *(float2*)&out[(size_t)(gm + 8) * OUT_F + gn] = v1;
        }
}

// ---------------- host: tensormap construction ----------------
typedef CUresult (*EncodeFn)(CUtensorMap*, CUtensorMapDataType, cuuint32_t, void*,
                             const cuuint64_t*, const cuuint64_t*, const cuuint32_t*,
                             const cuuint32_t*, CUtensorMapInterleave, CUtensorMapSwizzle,
                             CUtensorMapL2promotion, CUtensorMapFloatOOBfill);

static void encode_map(EncodeFn enc, CUtensorMap* m, void* ptr, int rows) {
    cuuint64_t dims[2]    = {(cuuint64_t)IN_F, (cuuint64_t)rows};
    cuuint64_t strides[1] = {(cuuint64_t)IN_F * 2};
    cuuint32_t box[2]     = {(cuuint32_t)KCH, 128};
    cuuint32_t estr[2]    = {1, 1};
    enc(m, CU_TENSOR_MAP_DATA_TYPE_BFLOAT16, 2, ptr, dims, strides, box, estr,
        CU_TENSOR_MAP_INTERLEAVE_NONE, CU_TENSOR_MAP_SWIZZLE_128B,
        CU_TENSOR_MAP_L2_PROMOTION_L2_128B, CU_TENSOR_MAP_FLOAT_OOB_FILL_NONE);
}

extern "C" void kernel_launch(void* const* d_in, const int* in_sizes, int n_in,
                              void* d_out, int out_size) {
    const float* x    = (const float*)d_in[0];
    const float* wgt  = (const float*)d_in[1];
    const float* bias = (const float*)d_in[2];
    const float* wn   = (const float*)d_in[3];
    const float* nx   = (const float*)d_in[4];
    const int*   perms= (const int*)  d_in[5];
    const float* mats = (const float*)d_in[6];
    float* out = (float*)d_out;

    make_wmats_kernel<<<(ROUNDS * GROUPS + 255) / 256, 256>>>(mats);
    split_x_kernel<<<4096, 256>>>(x, nx);
    split_w_kernel<<<512, 256>>>(wgt, wn);

    prep_kernel<<<dim3(BSZ / 32, IN_F / 32), dim3(32, 8)>>>(x, nx, 0);
    prep_kernel<<<dim3(OUT_F / 32, IN_F / 32), dim3(32, 8)>>>(wgt, wn, BSZ);

    for (int r = 0; r < ROUNDS; r++) {
        round_kernel<<<dim3((COLS4 + 255) / 256, GROUPS), 256>>>(
            r & 1, r, perms + r * IN_F, mats + (size_t)r * GROUPS * 4);
    }

    reset_kernel<<<1, 32>>>();
    minmax_kernel<<<1024, 256>>>();
    qparams_kernel<<<1, 32>>>();
    quantT_kernel<<<dim3(COLS / 32, IN_F / 32), dim3(32, 8)>>>();

    void* fp = nullptr;
#if CUDART_VERSION >= 12050
    cudaDriverEntryPointQueryResult qr;
    cudaGetDriverEntryPointByVersion("cuTensorMapEncodeTiled", &fp, 12000,
                                     cudaEnableDefault, &qr);
#else
    cudaGetDriverEntryPoint("cuTensorMapEncodeTiled", &fp, cudaEnableDefault);
#endif
    EncodeFn enc = (EncodeFn)fp;

    void *p_qx, *p_xhi, *p_xlo, *p_nxhi, *p_nxlo, *p_qw, *p_wnhi, *p_wnlo, *p_wphi, *p_wplo;
    cudaGetSymbolAddress(&p_qx, g_qx);     cudaGetSymbolAddress(&p_xhi, g_xhi);
    cudaGetSymbolAddress(&p_xlo, g_xlo);   cudaGetSymbolAddress(&p_nxhi, g_nxhi);
    cudaGetSymbolAddress(&p_nxlo, g_nxlo); cudaGetSymbolAddress(&p_qw, g_qw);
    cudaGetSymbolAddress(&p_wnhi, g_wnhi); cudaGetSymbolAddress(&p_wnlo, g_wnlo);
    cudaGetSymbolAddress(&p_wphi, g_wphi); cudaGetSymbolAddress(&p_wplo, g_wplo);

    TmapPack tp;
    encode_map(enc, &tp.a[0], p_qx,   BSZ);
    encode_map(enc, &tp.a[1], p_xhi,  BSZ);
    encode_map(enc, &tp.a[2], p_xlo,  BSZ);
    encode_map(enc, &tp.a[3], p_nxhi, BSZ);
    encode_map(enc, &tp.a[4], p_nxlo, BSZ);
    encode_map(enc, &tp.b[0], p_qw,   OUT_F);
    encode_map(enc, &tp.b[1], p_wnhi, OUT_F);
    encode_map(enc, &tp.b[2], p_wnlo, OUT_F);
    encode_map(enc, &tp.b[3], p_wphi, OUT_F);
    encode_map(enc, &tp.b[4], p_wplo, OUT_F);

    cudaFuncSetAttribute(gemm_tma_kernel, cudaFuncAttributeMaxDynamicSharedMemorySize, DSMEM);
    gemm_tma_kernel<<<dim3(OUT_F / 128, BSZ / 128), 256, DSMEM>>>(tp, bias, out);
}

// round 10
// speedup vs baseline: 2.9251x; 1.0925x over previous
#include <cuda_runtime.h>
#include <cuda.h>
#include <cuda_bf16.h>
#include <math.h>
#include <stdint.h>

#define IN_F   4096
#define OUT_F  1024
#define BSZ    8192
#define COLS   9216
#define COLS4  2304
#define GROUPS 2048
#define ROUNDS 12

#define KCH    64
#define CHPS   64             // chunks per segment
#define NSEG   7
#define NCH    (NSEG * CHPS)  // 448
#define NSTG   3
#define A_BYTES 32768         // 256 x 64 bf16
#define B_BYTES 16384         // 128 x 64 bf16
#define ST_BYTES (A_BYTES + B_BYTES)
#define DSMEM (1024 + NSTG * ST_BYTES)   // 148480

// ---------------- device scratch ----------------
__device__ __align__(128) float g_a[(size_t)IN_F * COLS];
__device__ __align__(128) float g_b[(size_t)IN_F * COLS];
__device__ __align__(128) float g_wmats[ROUNDS * GROUPS * 4];
__device__ unsigned g_mm[4];
__device__ float    g_qp[4];

__device__ __align__(128) __nv_bfloat16 g_qx  [(size_t)BSZ   * IN_F];
__device__ __align__(128) __nv_bfloat16 g_qw  [(size_t)OUT_F * IN_F];
__device__ __align__(128) __nv_bfloat16 g_xhi [(size_t)BSZ   * IN_F];
__device__ __align__(128) __nv_bfloat16 g_xlo [(size_t)BSZ   * IN_F];
__device__ __align__(128) __nv_bfloat16 g_nxhi[(size_t)BSZ   * IN_F];
__device__ __align__(128) __nv_bfloat16 g_nxlo[(size_t)BSZ   * IN_F];
__device__ __align__(128) __nv_bfloat16 g_wnhi[(size_t)OUT_F * IN_F];
__device__ __align__(128) __nv_bfloat16 g_wnlo[(size_t)OUT_F * IN_F];
__device__ __align__(128) __nv_bfloat16 g_wphi[(size_t)OUT_F * IN_F];
__device__ __align__(128) __nv_bfloat16 g_wplo[(size_t)OUT_F * IN_F];

struct TmapPack { CUtensorMap a[5]; CUtensorMap b[5]; };

// ---------------- helpers ----------------
__device__ __forceinline__ unsigned enc_f(float f) {
    unsigned u = __float_as_uint(f);
    return (u & 0x80000000u) ? ~u : (u | 0x80000000u);
}
__device__ __forceinline__ float dec_f(unsigned k) {
    return __uint_as_float((k & 0x80000000u) ? (k ^ 0x80000000u) : ~k);
}
__device__ __forceinline__ uint32_t smem_u32(const void* p) {
    uint32_t a;
    asm("{ .reg .u64 t; cvta.to.shared.u64 t, %1; cvt.u32.u64 %0, t; }" : "=r"(a) : "l"(p));
    return a;
}
__device__ __forceinline__ void split1(float v, __nv_bfloat16& h, __nv_bfloat16& l) {
    h = __float2bfloat16_rn(v);
    l = __float2bfloat16_rn(__fsub_rn(v, __bfloat162float(h)));
}

#define MBAR_INIT(addr, cnt) \
    asm volatile("mbarrier.init.shared.b64 [%0], %1;" :: "r"(addr), "r"(cnt) : "memory")
#define MBAR_EXPECT_TX(addr, bytes) \
    asm volatile("mbarrier.arrive.expect_tx.shared.b64 _, [%0], %1;" :: "r"(addr), "r"(bytes) : "memory")
#define MBAR_WAIT(addr, par) do {                                              \
    asm volatile(                                                              \
        "{\n\t.reg .pred P;\n\t"                                               \
        "WL_%=:\n\t"                                                           \
        "mbarrier.try_wait.parity.acquire.cta.shared::cta.b64 P, [%0], %1, 0x989680;\n\t" \
        "@P bra.uni WD_%=;\n\t"                                                \
        "bra.uni WL_%=;\n\t"                                                   \
        "WD_%=:\n\t}"                                                          \
        :: "r"(addr), "r"(par) : "memory");                                    \
} while (0)

#define TMA_2D(smem, map, cx, cy, mbar) \
    asm volatile("cp.async.bulk.tensor.2d.shared::cta.global.tile.mbarrier::complete_tx::bytes " \
                 "[%0], [%1, {%2, %3}], [%4];" \
                 :: "r"(smem), "l"(map), "r"(cx), "r"(cy), "r"(mbar) : "memory")

// ---------------- inv(m)^T via LU w/ partial pivoting ----------------
__global__ void make_wmats_kernel(const float* __restrict__ mats) {
    int idx = blockIdx.x * blockDim.x + threadIdx.x;
    if (idx >= ROUNDS * GROUPS) return;
    const float* m = mats + (size_t)idx * 4;
    float a = m[0], b = m[1], c = m[2], d = m[3];
    float i00, i01, i10, i11;
    if (fabsf(c) > fabsf(a)) {
        float l   = __fdiv_rn(a, c);
        float u22 = __fmaf_rn(-l, d, b);
        float x2c1 = __fdiv_rn(1.0f, u22);
        float x1c1 = __fdiv_rn(__fmul_rn(-d, x2c1), c);
        float x2c2 = __fdiv_rn(-l, u22);
        float x1c2 = __fdiv_rn(__fmaf_rn(-d, x2c2, 1.0f), c);
        i00 = x1c1; i01 = x1c2; i10 = x2c1; i11 = x2c2;
    } else {
        float l   = __fdiv_rn(c, a);
        float u22 = __fmaf_rn(-l, b, d);
        float x2c1 = __fdiv_rn(-l, u22);
        float x1c1 = __fdiv_rn(__fmaf_rn(-b, x2c1, 1.0f), a);
        float x2c2 = __fdiv_rn(1.0f, u22);
        float x1c2 = __fdiv_rn(__fmul_rn(-b, x2c2), a);
        i00 = x1c1; i01 = x1c2; i10 = x2c1; i11 = x2c2;
    }
    float* o = g_wmats + (size_t)idx * 4;
    o[0] = i00; o[1] = i10; o[2] = i01; o[3] = i11;
}

// ---------------- fused transpose+add + bf16 splits ----------------
__global__ void prepsplit_x_kernel(const float* __restrict__ x, const float* __restrict__ nx) {
    __shared__ float tile[32][33];
    int c0 = blockIdx.x * 32, k0 = blockIdx.y * 32;
    int tx = threadIdx.x, ty = threadIdx.y;
#pragma unroll
    for (int i = ty; i < 32; i += 8) {
        size_t idx = (size_t)(c0 + i) * IN_F + k0 + tx;
        float vx = x[idx], vn = nx[idx];
        tile[i][tx] = __fadd_rn(vx, vn);
        __nv_bfloat16 h, l;
        split1(vx, h, l); g_xhi[idx]  = h; g_xlo[idx]  = l;
        split1(vn, h, l); g_nxhi[idx] = h; g_nxlo[idx] = l;
    }
    __syncthreads();
#pragma unroll
    for (int i = ty; i < 32; i += 8)
        g_a[(size_t)(k0 + i) * COLS + c0 + tx] = tile[tx][i];
}
__global__ void prepsplit_w_kernel(const float* __restrict__ w, const float* __restrict__ wn) {
    __shared__ float tile[32][33];
    int c0 = blockIdx.x * 32, k0 = blockIdx.y * 32;
    int tx = threadIdx.x, ty = threadIdx.y;
#pragma unroll
    for (int i = ty; i < 32; i += 8) {
        size_t idx = (size_t)(c0 + i) * IN_F + k0 + tx;
        float vw = w[idx], vn = wn[idx];
        float vp = __fadd_rn(vw, vn);
        tile[i][tx] = vp;
        __nv_bfloat16 h, l;
        split1(vn, h, l); g_wnhi[idx] = h; g_wnlo[idx] = l;
        split1(vp, h, l); g_wphi[idx] = h; g_wplo[idx] = l;
    }
    __syncthreads();
#pragma unroll
    for (int i = ty; i < 32; i += 8)
        g_a[(size_t)(k0 + i) * COLS + BSZ + c0 + tx] = tile[tx][i];
}

// ---------------- TWO fused permutation + 2x2-mix rounds (bitwise-exact, NO FMA) ----
// Last pass also folds in the global min/max reduction (do_mm).
__global__ void round2_kernel(int dir, int r,
                              const int* __restrict__ perm0,
                              const int* __restrict__ perm1,
                              const float* __restrict__ matsx0,
                              const float* __restrict__ matsx1,
                              int do_mm) {
    const float* in  = dir ? g_b : g_a;
    float*       out = dir ? g_a : g_b;
    int g   = blockIdx.y;
    int col = blockIdx.x * 256 + threadIdx.x;   // COLS4 = 9*256, all valid
    int i0 = __ldg(&perm1[2 * g]);
    int i1 = __ldg(&perm1[2 * g + 1]);
    int g0 = i0 >> 1, p0 = i0 & 1;
    int g1 = i1 >> 1, p1 = i1 & 1;
    int ra0 = __ldg(&perm0[2 * g0]), rb0 = __ldg(&perm0[2 * g0 + 1]);
    int ra1 = __ldg(&perm0[2 * g1]), rb1 = __ldg(&perm0[2 * g1 + 1]);
    bool isx = (col < BSZ / 4);
    const float* m0base = isx ? matsx0 : (g_wmats + (size_t)r * GROUPS * 4);
    const float* m1base = isx ? matsx1 : (g_wmats + (size_t)(r + 1) * GROUPS * 4);
    float4 mA = __ldg((const float4*)(m0base + (size_t)g0 * 4));
    float4 mB = __ldg((const float4*)(m0base + (size_t)g1 * 4));
    float4 mC = __ldg((const float4*)(m1base + (size_t)g * 4));
    float c00 = p0 ? mA.z : mA.x, c01 = p0 ? mA.w : mA.y;
    float c10 = p1 ? mB.z : mB.x, c11 = p1 ? mB.w : mB.y;
    float4 a0 = ((const float4*)(in + (size_t)ra0 * COLS))[col];
    float4 b0 = ((const float4*)(in + (size_t)rb0 * COLS))[col];
    float4 a1 = ((const float4*)(in + (size_t)ra1 * COLS))[col];
    float4 b1 = ((const float4*)(in + (size_t)rb1 * COLS))[col];
    float4 v0, v1, o0, o1;
    v0.x = __fadd_rn(__fmul_rn(c00, a0.x), __fmul_rn(c01, b0.x));
    v0.y = __fadd_rn(__fmul_rn(c00, a0.y), __fmul_rn(c01, b0.y));
    v0.z = __fadd_rn(__fmul_rn(c00, a0.z), __fmul_rn(c01, b0.z));
    v0.w = __fadd_rn(__fmul_rn(c00, a0.w), __fmul_rn(c01, b0.w));
    v1.x = __fadd_rn(__fmul_rn(c10, a1.x), __fmul_rn(c11, b1.x));
    v1.y = __fadd_rn(__fmul_rn(c10, a1.y), __fmul_rn(c11, b1.y));
    v1.z = __fadd_rn(__fmul_rn(c10, a1.z), __fmul_rn(c11, b1.z));
    v1.w = __fadd_rn(__fmul_rn(c10, a1.w), __fmul_rn(c11, b1.w));
    o0.x = __fadd_rn(__fmul_rn(mC.x, v0.x), __fmul_rn(mC.y, v1.x));
    o0.y = __fadd_rn(__fmul_rn(mC.x, v0.y), __fmul_rn(mC.y, v1.y));
    o0.z = __fadd_rn(__fmul_rn(mC.x, v0.z), __fmul_rn(mC.y, v1.z));
    o0.w = __fadd_rn(__fmul_rn(mC.x, v0.w), __fmul_rn(mC.y, v1.w));
    o1.x = __fadd_rn(__fmul_rn(mC.z, v0.x), __fmul_rn(mC.w, v1.x));
    o1.y = __fadd_rn(__fmul_rn(mC.z, v0.y), __fmul_rn(mC.w, v1.y));
    o1.z = __fadd_rn(__fmul_rn(mC.z, v0.z), __fmul_rn(mC.w, v1.z));
    o1.w = __fadd_rn(__fmul_rn(mC.z, v0.w), __fmul_rn(mC.w, v1.w));
    ((float4*)(out + (size_t)(2 * g)     * COLS))[col] = o0;
    ((float4*)(out + (size_t)(2 * g + 1) * COLS))[col] = o1;

    if (do_mm) {   // block is uniformly x (blocks 0-7) or w (block 8)
        float lo = fminf(fminf(fminf(o0.x, o0.y), fminf(o0.z, o0.w)),
                         fminf(fminf(o1.x, o1.y), fminf(o1.z, o1.w)));
        float hi = fmaxf(fmaxf(fmaxf(o0.x, o0.y), fmaxf(o0.z, o0.w)),
                         fmaxf(fmaxf(o1.x, o1.y), fmaxf(o1.z, o1.w)));
        __shared__ float red[256];
        red[threadIdx.x] = lo;
        __syncthreads();
        for (int s = 128; s > 0; s >>= 1) {
            if (threadIdx.x < s) red[threadIdx.x] = fminf(red[threadIdx.x], red[threadIdx.x + s]);
            __syncthreads();
        }
        if (threadIdx.x == 0) atomicMin(&g_mm[isx ? 0 : 2], enc_f(red[0]));
        __syncthreads();
        red[threadIdx.x] = hi;
        __syncthreads();
        for (int s = 128; s > 0; s >>= 1) {
            if (threadIdx.x < s) red[threadIdx.x] = fmaxf(red[threadIdx.x], red[threadIdx.x + s]);
            __syncthreads();
        }
        if (threadIdx.x == 0) atomicMax(&g_mm[isx ? 1 : 3], enc_f(red[0]));
    }
}

// ---------------- reset + qparams ----------------
__global__ void reset_kernel() {
    if (threadIdx.x == 0) {
        g_mm[0] = 0xFFFFFFFFu; g_mm[1] = 0u;
        g_mm[2] = 0xFFFFFFFFu; g_mm[3] = 0u;
    }
}
__global__ void qparams_kernel() {
    if (threadIdx.x == 0) {
        float lx = dec_f(g_mm[0]), hx = dec_f(g_mm[1]);
        float sx = __fdiv_rn(__fsub_rn(hx, lx), 255.0f);
        float zx = rintf(__fsub_rn(-128.0f, __fdiv_rn(lx, sx)));
        float lw = dec_f(g_mm[2]), hw = dec_f(g_mm[3]);
        float sw = __fdiv_rn(__fsub_rn(hw, lw), 255.0f);
        float zw = rintf(__fsub_rn(-128.0f, __fdiv_rn(lw, sw)));
        g_qp[0] = sx; g_qp[1] = zx; g_qp[2] = sw; g_qp[3] = zw;
    }
}

// ---------------- quantize -> integer (q - zp) bf16, K-major ----------------
__global__ void quantT_kernel() {
    __shared__ float tile[32][33];
    int c0 = blockIdx.x * 32, k0 = blockIdx.y * 32;
    int tx = threadIdx.x, ty = threadIdx.y;
    bool isx = (c0 < BSZ);
    float s = isx ? g_qp[0] : g_qp[2];
    float z = isx ? g_qp[1] : g_qp[3];
#pragma unroll
    for (int i = ty; i < 32; i += 8) {
        float t = g_a[(size_t)(k0 + i) * COLS + c0 + tx];
        float q = rintf(__fadd_rn(__fdiv_rn(t, s), z));
        q = fminf(fmaxf(q, -128.0f), 127.0f);
        tile[i][tx] = __fsub_rn(q, z);
    }
    __syncthreads();
    __nv_bfloat16* dst = isx ? g_qx : g_qw;
    int cb = isx ? c0 : (c0 - BSZ);
#pragma unroll
    for (int i = ty; i < 32; i += 8) {
        dst[(size_t)(cb + i) * IN_F + k0 + tx] = __float2bfloat16_rn(tile[tx][i]);
    }
}

// ---------------- TMA-fed mma.sync GEMM, tile 256x128 ----------------
// segs: 0:(qx,qw) ; 1..6: (xhi,wnhi)(xhi,wnlo)(xlo,wnhi)(nxhi,wphi)(nxhi,wplo)(nxlo,wphi)
// acc = Sum_q ; at seg0 end acc *= -sx*sw ; then acc += corr ; out = bias - acc
__global__ void __launch_bounds__(512)
gemm_tma_kernel(const __grid_constant__ TmapPack tp,
                const float* __restrict__ bias, float* __restrict__ out) {
    extern __shared__ __align__(1024) char smem[];
    uint32_t sb = smem_u32(smem);
    const int tid = threadIdx.x, lane = tid & 31, warp = tid >> 5;
    const int bn = blockIdx.x, bm = blockIdx.y;
    const int wm = (warp >> 2) * 64, wn = (warp & 3) * 32;

    if (tid == 0) {
#pragma unroll
        for (int i = 0; i < NSTG; i++) MBAR_INIT(sb + i * 8, 1);
    }
    __syncthreads();

    float acc[4][4][4];
#pragma unroll
    for (int a = 0; a < 4; a++)
#pragma unroll
        for (int b = 0; b < 4; b++)
#pragma unroll
            for (int c = 0; c < 4; c++) acc[a][b][c] = 0.0f;

    const float nss = -__fmul_rn(g_qp[0], g_qp[2]);

    static const int asel[NSEG] = {0, 1, 1, 2, 3, 3, 4};
    static const int bsel[NSEG] = {0, 1, 2, 1, 3, 4, 3};

    if (tid == 0) {
#pragma unroll
        for (int p = 0; p < NSTG; p++) {
            int kx = p * KCH;   // p < 3 -> seg 0
            uint32_t st = sb + 1024 + p * ST_BYTES;
            MBAR_EXPECT_TX(sb + p * 8, ST_BYTES);
            TMA_2D(st,           &tp.a[0], kx, bm * 256, sb + p * 8);
            TMA_2D(st + A_BYTES, &tp.b[0], kx, bn * 128, sb + p * 8);
        }
    }

    for (int c = 0; c < NCH; c++) {
        int s = c % NSTG, ph = (c / NSTG) & 1;
        MBAR_WAIT(sb + s * 8, ph);
        uint32_t abase = sb + 1024 + s * ST_BYTES;
        uint32_t bbase = abase + A_BYTES;
#pragma unroll
        for (int kq = 0; kq < 4; kq++) {
            uint32_t af[4][4], bf[4][2];
#pragma unroll
            for (int mt = 0; mt < 4; mt++) {
                int row = wm + mt * 16 + (lane & 15);
                int chk = kq * 2 + (lane >> 4);
                uint32_t off = (uint32_t)(row * 128 + chk * 16);
                uint32_t ad = abase + (off ^ ((off >> 3) & 0x70));
                asm volatile("ldmatrix.sync.aligned.m8n8.x4.shared.b16 {%0,%1,%2,%3},[%4];"
                             : "=r"(af[mt][0]), "=r"(af[mt][1]), "=r"(af[mt][2]), "=r"(af[mt][3])
                             : "r"(ad));
            }
#pragma unroll
            for (int nt = 0; nt < 4; nt++) {
                int row = wn + nt * 8 + (lane & 7);
                int chk = kq * 2 + ((lane >> 3) & 1);
                uint32_t off = (uint32_t)(row * 128 + chk * 16);
                uint32_t bd = bbase + (off ^ ((off >> 3) & 0x70));
                asm volatile("ldmatrix.sync.aligned.m8n8.x2.shared.b16 {%0,%1},[%2];"
                             : "=r"(bf[nt][0]), "=r"(bf[nt][1]) : "r"(bd));
            }
#pragma unroll
            for (int mt = 0; mt < 4; mt++)
#pragma unroll
                for (int nt = 0; nt < 4; nt++) {
                    asm volatile(
                        "mma.sync.aligned.m16n8k16.row.col.f32.bf16.bf16.f32 "
                        "{%0,%1,%2,%3},{%4,%5,%6,%7},{%8,%9},{%0,%1,%2,%3};"
                        : "+f"(acc[mt][nt][0]), "+f"(acc[mt][nt][1]),
                          "+f"(acc[mt][nt][2]), "+f"(acc[mt][nt][3])
                        : "r"(af[mt][0]), "r"(af[mt][1]), "r"(af[mt][2]), "r"(af[mt][3]),
                          "r"(bf[nt][0]), "r"(bf[nt][1]));
                }
        }
        if (c == CHPS - 1) {
#pragma unroll
            for (int a = 0; a < 4; a++)
#pragma unroll
                for (int b = 0; b < 4; b++)
#pragma unroll
                    for (int q = 0; q < 4; q++) acc[a][b][q] = __fmul_rn(acc[a][b][q], nss);
        }
        __syncthreads();
        if (tid == 0 && c + NSTG < NCH) {
            int nc = c + NSTG;
            int seg = nc >> 6, kx = (nc & 63) * KCH;
            uint32_t st = sb + 1024 + s * ST_BYTES;
            MBAR_EXPECT_TX(sb + s * 8, ST_BYTES);
            TMA_2D(st,           &tp.a[asel[seg]], kx, bm * 256, sb + s * 8);
            TMA_2D(st + A_BYTES, &tp.b[bsel[seg]], kx, bn * 128, sb + s * 8);
        }
    }

    // epilogue: out = bias - acc
    const int grp = lane >> 2, tig = lane & 3;
#pragma unroll
    for (int mt = 0; mt < 4; mt++)
#pragma unroll
        for (int nt = 0; nt < 4; nt++) {
            int gm = bm * 256 + wm + mt * 16 + grp;
            int gn = bn * 128 + wn + nt * 8 + tig * 2;
            float b0 = bias[gn], b1 = bias[gn + 1];
            float2 v0, v1;
            v0.x = __fsub_rn(b0, acc[mt][nt][0]);
            v0.y = __fsub_rn(b1, acc[mt][nt][1]);
            v1.x = __fsub_rn(b0, acc[mt][nt][2]);
            v1.y = __fsub_rn(b1, acc[mt][nt][3]);
            *(float2*)&out[(size_t)gm * OUT_F + gn]       = v0;
            *(float2*)&out[(size_t)(gm + 8) * OUT_F + gn] = v1;
        }
}

// ---------------- host: tensormap construction ----------------
typedef CUresult (*EncodeFn)(CUtensorMap*, CUtensorMapDataType, cuuint32_t, void*,
                             const cuuint64_t*, const cuuint64_t*, const cuuint32_t*,
                             const cuuint32_t*, CUtensorMapInterleave, CUtensorMapSwizzle,
                             CUtensorMapL2promotion, CUtensorMapFloatOOBfill);

static void encode_map(EncodeFn enc, CUtensorMap* m, void* ptr, int rows, int boxrows) {
    cuuint64_t dims[2]    = {(cuuint64_t)IN_F, (cuuint64_t)rows};
    cuuint64_t strides[1] = {(cuuint64_t)IN_F * 2};
    cuuint32_t box[2]     = {(cuuint32_t)KCH, (cuuint32_t)boxrows};
    cuuint32_t estr[2]    = {1, 1};
    enc(m, CU_TENSOR_MAP_DATA_TYPE_BFLOAT16, 2, ptr, dims, strides, box, estr,
        CU_TENSOR_MAP_INTERLEAVE_NONE, CU_TENSOR_MAP_SWIZZLE_128B,
        CU_TENSOR_MAP_L2_PROMOTION_L2_128B, CU_TENSOR_MAP_FLOAT_OOB_FILL_NONE);
}

extern "C" void kernel_launch(void* const* d_in, const int* in_sizes, int n_in,
                              void* d_out, int out_size) {
    const float* x    = (const float*)d_in[0];
    const float* wgt  = (const float*)d_in[1];
    const float* bias = (const float*)d_in[2];
    const float* wn   = (const float*)d_in[3];
    const float* nx   = (const float*)d_in[4];
    const int*   perms= (const int*)  d_in[5];
    const float* mats = (const float*)d_in[6];
    float* out = (float*)d_out;

    make_wmats_kernel<<<(ROUNDS * GROUPS + 255) / 256, 256>>>(mats);
    reset_kernel<<<1, 32>>>();

    prepsplit_x_kernel<<<dim3(BSZ / 32, IN_F / 32), dim3(32, 8)>>>(x, nx);
    prepsplit_w_kernel<<<dim3(OUT_F / 32, IN_F / 32), dim3(32, 8)>>>(wgt, wn);

    // 6 fused passes (2 rounds each); last pass also does min/max
    for (int p = 0; p < ROUNDS / 2; p++) {
        int r = 2 * p;
        round2_kernel<<<dim3(COLS4 / 256, GROUPS), 256>>>(
            p & 1, r,
            perms + (size_t)r * IN_F, perms + (size_t)(r + 1) * IN_F,
            mats + (size_t)r * GROUPS * 4, mats + (size_t)(r + 1) * GROUPS * 4,
            (p == ROUNDS / 2 - 1) ? 1 : 0);
    }

    qparams_kernel<<<1, 32>>>();
    quantT_kernel<<<dim3(COLS / 32, IN_F / 32), dim3(32, 8)>>>();

    void* fp = nullptr;
#if CUDART_VERSION >= 12050
    cudaDriverEntryPointQueryResult qr;
    cudaGetDriverEntryPointByVersion("cuTensorMapEncodeTiled", &fp, 12000,
                                     cudaEnableDefault, &qr);
#else
    cudaGetDriverEntryPoint("cuTensorMapEncodeTiled", &fp, cudaEnableDefault);
#endif
    EncodeFn enc = (EncodeFn)fp;

    void *p_qx, *p_xhi, *p_xlo, *p_nxhi, *p_nxlo, *p_qw, *p_wnhi, *p_wnlo, *p_wphi, *p_wplo;
    cudaGetSymbolAddress(&p_qx, g_qx);     cudaGetSymbolAddress(&p_xhi, g_xhi);
    cudaGetSymbolAddress(&p_xlo, g_xlo);   cudaGetSymbolAddress(&p_nxhi, g_nxhi);
    cudaGetSymbolAddress(&p_nxlo, g_nxlo); cudaGetSymbolAddress(&p_qw, g_qw);
    cudaGetSymbolAddress(&p_wnhi, g_wnhi); cudaGetSymbolAddress(&p_wnlo, g_wnlo);
    cudaGetSymbolAddress(&p_wphi, g_wphi); cudaGetSymbolAddress(&p_wplo, g_wplo);

    TmapPack tp;
    encode_map(enc, &tp.a[0], p_qx,   BSZ,   256);
    encode_map(enc, &tp.a[1], p_xhi,  BSZ,   256);
    encode_map(enc, &tp.a[2], p_xlo,  BSZ,   256);
    encode_map(enc, &tp.a[3], p_nxhi, BSZ,   256);
    encode_map(enc, &tp.a[4], p_nxlo, BSZ,   256);
    encode_map(enc, &tp.b[0], p_qw,   OUT_F, 128);
    encode_map(enc, &tp.b[1], p_wnhi, OUT_F, 128);
    encode_map(enc, &tp.b[2], p_wnlo, OUT_F, 128);
    encode_map(enc, &tp.b[3], p_wphi, OUT_F, 128);
    encode_map(enc, &tp.b[4], p_wplo, OUT_F, 128);

    cudaFuncSetAttribute(gemm_tma_kernel, cudaFuncAttributeMaxDynamicSharedMemorySize, DSMEM);
    gemm_tma_kernel<<<dim3(OUT_F / 128, BSZ / 256), 512, DSMEM>>>(tp, bias, out);
}